// round 12
// baseline (speedup 1.0000x reference)
#include <cuda_runtime.h>
#include <cuda_fp16.h>
#include <math.h>
#include <stdint.h>

// ---------------- problem constants ----------------
#define S_   2048
#define HID_ 2048
#define H_   16
#define NOPE_ 128
#define ROPE_ 64
#define VD_  128
#define QH_  192
#define QL_  1536
#define KVL_ 512
#define CKV_ 576
#define INTER_ 8192
#define HQH_ 3072
#define KVOUT_ 256
#define KFD_ 192

// ---------------- scratch byte offsets ----------------
#define OB_SCORES   0L
#define OB_P        268435456L
#define OB_H1       402653184L
#define OB_QA       411041792L
#define OB_Q        417333248L
#define OB_CKV      429916160L
#define OB_KVLN     432275456L
#define OB_KV       434372608L
#define OB_KFT      435421184L
#define OB_V2       436207616L
#define OB_ATTNO    436731904L
#define OB_ATTNPROJ 445120512L
#define OB_X        461897728L
#define OB_H2       478674944L
#define OB_GU       487063552L
#define OB_ACT      554172416L
#define OB_MLP      587726848L
#define OB_WQA      604504064L
#define OB_WQB      610795520L
#define OB_WKV      620232704L
#define OB_WKVI     622592000L
#define OB_WO       622854144L
#define OB_WGU      631242752L
#define OB_WDN      698351616L
#define SCRATCH_BYTES 732000000L

__device__ __align__(256) unsigned char g_scratch[SCRATCH_BYTES];

__device__ __forceinline__ uint32_t pack_half2(float a, float b) {
    __half2 h = __floats2half2_rn(a, b);
    return *(uint32_t*)&h;
}

// ---------------- reductions ----------------
__device__ __forceinline__ float warp_sum(float v) {
    #pragma unroll
    for (int o = 16; o > 0; o >>= 1) v += __shfl_xor_sync(0xffffffffu, v, o);
    return v;
}
__device__ __forceinline__ float warp_max(float v) {
    #pragma unroll
    for (int o = 16; o > 0; o >>= 1) v = fmaxf(v, __shfl_xor_sync(0xffffffffu, v, o));
    return v;
}
__device__ float block_sum(float v) {
    __shared__ float sh[32];
    int lane = threadIdx.x & 31, wid = threadIdx.x >> 5, nw = (blockDim.x + 31) >> 5;
    v = warp_sum(v);
    __syncthreads();
    if (lane == 0) sh[wid] = v;
    __syncthreads();
    if (wid == 0) {
        float x = (lane < nw) ? sh[lane] : 0.f;
        x = warp_sum(x);
        if (lane == 0) sh[0] = x;
    }
    __syncthreads();
    return sh[0];
}
__device__ float block_max(float v) {
    __shared__ float sh[32];
    int lane = threadIdx.x & 31, wid = threadIdx.x >> 5, nw = (blockDim.x + 31) >> 5;
    v = warp_max(v);
    __syncthreads();
    if (lane == 0) sh[wid] = v;
    __syncthreads();
    if (wid == 0) {
        float x = (lane < nw) ? sh[lane] : -3.4e38f;
        x = warp_max(x);
        if (lane == 0) sh[0] = x;
    }
    __syncthreads();
    return sh[0];
}

// ---------------- weight conversion ----------------
__global__ void conv_w_kernel(const float* __restrict__ src, uint32_t* __restrict__ dst,
                              int K2, int Nout, int lds, int c0) {
    long i = (long)blockIdx.x * blockDim.x + threadIdx.x;
    long total = (long)K2 * (Nout >> 2);
    if (i >= total) return;
    int k2 = (int)(i / (Nout >> 2));
    int c  = (int)(i % (Nout >> 2)) << 2;
    float4 a = *(const float4*)(src + (long)(2 * k2) * lds + c0 + c);
    float4 b = *(const float4*)(src + (long)(2 * k2 + 1) * lds + c0 + c);
    uint4 o;
    o.x = pack_half2(a.x, b.x);
    o.y = pack_half2(a.y, b.y);
    o.z = pack_half2(a.z, b.z);
    o.w = pack_half2(a.w, b.w);
    *(uint4*)(dst + (long)k2 * Nout + c) = o;
}

// ---------------- elementwise / norm kernels ----------------
__global__ void rms_kernel(const float* __restrict__ in, const float* __restrict__ res,
                           const float* __restrict__ w, void* __restrict__ out,
                           int N, int outHalf) {
    int row = blockIdx.x;
    const float* x = in + (long)row * N;
    float sq = 0.f;
    for (int i = threadIdx.x; i < N; i += blockDim.x) { float v = x[i]; sq += v * v; }
    sq = block_sum(sq);
    float scale = rsqrtf(sq / (float)N + 1e-6f);
    const float* r = res ? res + (long)row * N : nullptr;
    if (outHalf) {
        __half* o = (__half*)out + (long)row * N;
        for (int i = threadIdx.x; i < N; i += blockDim.x)
            o[i] = __float2half_rn((r ? r[i] : 0.f) + x[i] * scale * w[i]);
    } else {
        float* o = (float*)out + (long)row * N;
        for (int i = threadIdx.x; i < N; i += blockDim.x)
            o[i] = (r ? r[i] : 0.f) + x[i] * scale * w[i];
    }
}

__global__ void ln_kernel(const __half* __restrict__ in, const float* __restrict__ s,
                          const float* __restrict__ b, __half* __restrict__ out,
                          int N, int ldin, int ldout) {
    int row = blockIdx.x;
    const __half* x = in + (long)row * ldin;
    float sum = 0.f, sq = 0.f;
    for (int i = threadIdx.x; i < N; i += blockDim.x) {
        float v = __half2float(x[i]);
        sum += v; sq += v * v;
    }
    sum = block_sum(sum);
    sq = block_sum(sq);
    float m = sum / (float)N;
    float var = sq / (float)N - m * m;
    float r = rsqrtf(var + 1e-6f);
    __half* o = out + (long)row * ldout;
    for (int i = threadIdx.x; i < N; i += blockDim.x)
        o[i] = __float2half_rn((__half2float(x[i]) - m) * r * s[i] + b[i]);
}

__global__ void rope_q_kernel(__half* __restrict__ q, const int* __restrict__ pos) {
    int srow = blockIdx.x;
    int t = threadIdx.x;
    int h = t >> 5, j = t & 31;
    float p = (float)pos[srow];
    float invf = __expf(-((float)(2 * j)) / 64.f * 9.210340371976184f);
    float sn, c;
    sincosf(p * invf, &sn, &c);
    long base = (long)srow * HQH_ + h * QH_ + NOPE_;
    float x1 = __half2float(q[base + j]);
    float x2 = __half2float(q[base + 32 + j]);
    q[base + j]      = __float2half_rn(x1 * c - x2 * sn);
    q[base + 32 + j] = __float2half_rn(x2 * c + x1 * sn);
}

__global__ void build_kft_kernel(const __half* __restrict__ kv, const __half* __restrict__ ckv,
                                 const int* __restrict__ pos, uint32_t* __restrict__ kft2) {
    int srow = blockIdx.x;
    int k2 = threadIdx.x;        // 0..95
    uint32_t val;
    if (k2 < 64) {
        val = *(const uint32_t*)(kv + (long)srow * KVOUT_ + 2 * k2);
    } else {
        const __half* kp = ckv + (long)srow * CKV_ + KVL_;
        float p = (float)pos[srow];
        float v[2];
        #pragma unroll
        for (int u = 0; u < 2; u++) {
            int idx = 2 * k2 + u - 128;
            int jj = (idx < 32) ? idx : idx - 32;
            float invf = __expf(-((float)(2 * jj)) / 64.f * 9.210340371976184f);
            float sn, c;
            sincosf(p * invf, &sn, &c);
            float a = __half2float(kp[jj]);
            float b2 = __half2float(kp[jj + 32]);
            v[u] = (idx < 32) ? (a * c - b2 * sn) : (b2 * c + a * sn);
        }
        val = pack_half2(v[0], v[1]);
    }
    kft2[(long)k2 * S_ + srow] = val;
}

__global__ void build_v2_kernel(const __half* __restrict__ kv, uint32_t* __restrict__ v2) {
    int i = blockIdx.x * blockDim.x + threadIdx.x;
    if (i >= (S_ / 2) * VD_) return;
    int k2 = i >> 7, n = i & 127;
    float a = __half2float(kv[(long)(2 * k2) * KVOUT_ + NOPE_ + n]);
    float b = __half2float(kv[(long)(2 * k2 + 1) * KVOUT_ + NOPE_ + n]);
    v2[i] = pack_half2(a, b);
}

__global__ void softmax_kernel(float* __restrict__ scores, __half* __restrict__ P) {
    int q = blockIdx.x, h = blockIdx.y;
    float* row = scores + ((long)h * S_ + q) * S_;
    __half* prow = P + ((long)h * S_ + q) * S_;
    float mx = -3.4e38f;
    for (int k = threadIdx.x; k <= q; k += blockDim.x)
        mx = fmaxf(mx, row[k]);
    mx = block_max(mx);
    float sum = 0.f;
    for (int k = threadIdx.x; k <= q; k += blockDim.x) {
        float e = __expf(row[k] - mx);
        row[k] = e;
        sum += e;
    }
    sum = block_sum(sum);
    float inv = 1.f / sum;
    for (int k = threadIdx.x; k <= q; k += blockDim.x)
        prow[k] = __float2half_rn(row[k] * inv);
    int kend = min(S_, (q & ~127) + 192);
    for (int k = q + 1 + threadIdx.x; k < kend; k += blockDim.x)
        prow[k] = __float2half_rn(0.f);
}

__global__ void silu_mul_kernel(const __half* __restrict__ gu, __half* __restrict__ act) {
    long idx = (long)blockIdx.x * blockDim.x + threadIdx.x;
    int srow = (int)(idx >> 13);
    int i = (int)(idx & 8191);
    float g = __half2float(gu[(long)srow * (2 * INTER_) + i]);
    float u = __half2float(gu[(long)srow * (2 * INTER_) + INTER_ + i]);
    act[idx] = __float2half_rn(u * g / (1.f + __expf(-g)));
}

// ---------------- FP16 GEMM common ----------------
__device__ __forceinline__ void cp_async16(uint32_t dst, const void* src, int szbytes) {
    asm volatile("cp.async.cg.shared.global [%0], [%1], 16, %2;\n"
                 :: "r"(dst), "l"(src), "r"(szbytes));
}

#define A_STRIDE_U32 20
#define B_STRIDE_U32 136
#define A_STAGE_B (128 * 80)
#define B_STAGE_B (16 * 544)
#define NSTAGE 3
#define GEMM_SMEM_BYTES (NSTAGE * (A_STAGE_B + B_STAGE_B))

// ---- 128x128 tile kernel (attention + small GEMMs) ----
__global__ __launch_bounds__(128) void h16gemm_kernel(
    const __half* __restrict__ A, const uint32_t* __restrict__ B2, void* __restrict__ Cv,
    int M, int N, int K, int lda, int ldb2, int ldc,
    long sA, long sB2, long sC, float alpha, int outHalf, int mode)
{
    const int bm = blockIdx.y * 128;
    const int bn = blockIdx.x * 128;
    if (mode == 1 && bn >= bm + 128) return;

    A  += (long)blockIdx.z * sA;
    B2 += (long)blockIdx.z * sB2;
    char* Cb = (char*)Cv + (long)blockIdx.z * sC * (outHalf ? 2 : 4);

    int ntiles = K >> 5;
    if (mode == 2) { int ke = (bm + 159) >> 5; if (ke < ntiles) ntiles = ke; }

    extern __shared__ __align__(16) char smem[];
    uint32_t smem_base = (uint32_t)__cvta_generic_to_shared(smem);
    const uint32_t a_base = smem_base;
    const uint32_t b_base = smem_base + NSTAGE * A_STAGE_B;

    const int t = threadIdx.x;
    const int warp = t >> 5;
    const int lane = t & 31;
    const int g  = lane >> 2;
    const int tg = lane & 3;
    const int wm = (warp & 1) * 64;
    const int wn = (warp >> 1) * 64;

    float acc[4][8][4];
    #pragma unroll
    for (int i = 0; i < 4; i++)
        #pragma unroll
        for (int j = 0; j < 8; j++)
            #pragma unroll
            for (int r = 0; r < 4; r++) acc[i][j][r] = 0.f;

    auto stage = [&](int kt) {
        int s = kt % NSTAGE;
        int k0 = kt << 5;
        uint32_t ao = a_base + (uint32_t)s * A_STAGE_B;
        #pragma unroll
        for (int it = 0; it < 4; it++) {
            int idx = t + 128 * it;
            int row = idx >> 2;
            int c   = idx & 3;
            cp_async16(ao + (uint32_t)(row * 80 + c * 16),
                       A + (long)(bm + row) * lda + k0 + c * 8, 16);
        }
        uint32_t bo = b_base + (uint32_t)s * B_STAGE_B;
        int k20 = kt << 4;
        #pragma unroll
        for (int it = 0; it < 4; it++) {
            int idx = t + 128 * it;
            int row = idx >> 5;
            int c4  = (idx & 31) * 4;
            int col = bn + c4;
            int sz = (col < N) ? 16 : 0;
            cp_async16(bo + (uint32_t)(row * 544 + c4 * 4),
                       B2 + (long)(k20 + row) * ldb2 + col, sz);
        }
    };

    stage(0);
    asm volatile("cp.async.commit_group;\n");
    stage(1);
    asm volatile("cp.async.commit_group;\n");

    for (int kt = 0; kt < ntiles; kt++) {
        asm volatile("cp.async.wait_group 1;\n");
        __syncthreads();

        const uint32_t* As = (const uint32_t*)(smem + (kt % NSTAGE) * A_STAGE_B);
        const uint32_t* Bs = (const uint32_t*)(smem + NSTAGE * A_STAGE_B + (kt % NSTAGE) * B_STAGE_B);

        #pragma unroll
        for (int kk2 = 0; kk2 < 16; kk2 += 8) {
            uint32_t af[4][4];
            #pragma unroll
            for (int i = 0; i < 4; i++) {
                int r0 = wm + 16 * i + g;
                af[i][0] = As[(r0)     * A_STRIDE_U32 + kk2 + tg];
                af[i][1] = As[(r0 + 8) * A_STRIDE_U32 + kk2 + tg];
                af[i][2] = As[(r0)     * A_STRIDE_U32 + kk2 + tg + 4];
                af[i][3] = As[(r0 + 8) * A_STRIDE_U32 + kk2 + tg + 4];
            }
            uint32_t bf[8][2];
            #pragma unroll
            for (int j = 0; j < 8; j++) {
                int c0 = wn + 8 * j + g;
                bf[j][0] = Bs[(kk2 + tg)     * B_STRIDE_U32 + c0];
                bf[j][1] = Bs[(kk2 + tg + 4) * B_STRIDE_U32 + c0];
            }
            #pragma unroll
            for (int i = 0; i < 4; i++)
                #pragma unroll
                for (int j = 0; j < 8; j++) {
                    asm volatile(
                        "mma.sync.aligned.m16n8k16.row.col.f32.f16.f16.f32 "
                        "{%0,%1,%2,%3}, {%4,%5,%6,%7}, {%8,%9}, {%0,%1,%2,%3};\n"
                        : "+f"(acc[i][j][0]), "+f"(acc[i][j][1]),
                          "+f"(acc[i][j][2]), "+f"(acc[i][j][3])
                        : "r"(af[i][0]), "r"(af[i][1]), "r"(af[i][2]), "r"(af[i][3]),
                          "r"(bf[j][0]), "r"(bf[j][1]));
                }
        }
        __syncthreads();
        if (kt + 2 < ntiles) stage(kt + 2);
        asm volatile("cp.async.commit_group;\n");
    }

    if (outHalf) {
        __half* C = (__half*)Cb;
        #pragma unroll
        for (int i = 0; i < 4; i++)
            #pragma unroll
            for (int j = 0; j < 8; j++) {
                int r0 = bm + wm + 16 * i + g;
                int c0 = bn + wn + 8 * j + 2 * tg;
                if (c0 < N) {
                    *(uint32_t*)(C + (long)r0 * ldc + c0) =
                        pack_half2(acc[i][j][0] * alpha, acc[i][j][1] * alpha);
                    *(uint32_t*)(C + (long)(r0 + 8) * ldc + c0) =
                        pack_half2(acc[i][j][2] * alpha, acc[i][j][3] * alpha);
                }
            }
    } else {
        float* C = (float*)Cb;
        #pragma unroll
        for (int i = 0; i < 4; i++)
            #pragma unroll
            for (int j = 0; j < 8; j++) {
                int r0 = bm + wm + 16 * i + g;
                int c0 = bn + wn + 8 * j + 2 * tg;
                if (c0 < N) {
                    *(float2*)(C + (long)r0 * ldc + c0) =
                        make_float2(acc[i][j][0] * alpha, acc[i][j][1] * alpha);
                    *(float2*)(C + (long)(r0 + 8) * ldc + c0) =
                        make_float2(acc[i][j][2] * alpha, acc[i][j][3] * alpha);
                }
            }
    }
}

// ---- 256x128 tile kernel (big weight GEMMs; halves A-side L2 traffic) ----
#define A256_STAGE_B (256 * 80)     // 20480
#define GEMM256_SMEM_BYTES (NSTAGE * (A256_STAGE_B + B_STAGE_B))   // 87552

__global__ __launch_bounds__(256) void h16gemm256_kernel(
    const __half* __restrict__ A, const uint32_t* __restrict__ B2, void* __restrict__ Cv,
    int M, int N, int K, int lda, int ldb2, int ldc, float alpha, int outHalf)
{
    const int bm = blockIdx.y * 256;
    const int bn = blockIdx.x * 128;

    char* Cb = (char*)Cv;
    const int ntiles = K >> 5;

    extern __shared__ __align__(16) char smem[];
    const uint32_t smem_base = (uint32_t)__cvta_generic_to_shared(smem);
    const uint32_t a_base = smem_base;
    const uint32_t b_base = smem_base + NSTAGE * A256_STAGE_B;

    const int t = threadIdx.x;
    const int warp = t >> 5;
    const int lane = t & 31;
    const int g  = lane >> 2;
    const int tg = lane & 3;
    const int wm = (warp & 3) * 64;     // 4 warps in m
    const int wn = (warp >> 2) * 64;    // 2 warps in n

    float acc[4][8][4];
    #pragma unroll
    for (int i = 0; i < 4; i++)
        #pragma unroll
        for (int j = 0; j < 8; j++)
            #pragma unroll
            for (int r = 0; r < 4; r++) acc[i][j][r] = 0.f;

    auto stage = [&](int kt) {
        int s = kt % NSTAGE;
        int k0 = kt << 5;
        uint32_t ao = a_base + (uint32_t)s * A256_STAGE_B;
        #pragma unroll
        for (int it = 0; it < 4; it++) {
            int idx = t + 256 * it;     // 0..1023
            int row = idx >> 2;         // 0..255
            int c   = idx & 3;
            cp_async16(ao + (uint32_t)(row * 80 + c * 16),
                       A + (long)(bm + row) * lda + k0 + c * 8, 16);
        }
        uint32_t bo = b_base + (uint32_t)s * B_STAGE_B;
        int k20 = kt << 4;
        #pragma unroll
        for (int it = 0; it < 2; it++) {
            int idx = t + 256 * it;     // 0..511
            int row = idx >> 5;         // 0..15
            int c4  = (idx & 31) * 4;
            int col = bn + c4;
            int sz = (col < N) ? 16 : 0;
            cp_async16(bo + (uint32_t)(row * 544 + c4 * 4),
                       B2 + (long)(k20 + row) * ldb2 + col, sz);
        }
    };

    stage(0);
    asm volatile("cp.async.commit_group;\n");
    stage(1);
    asm volatile("cp.async.commit_group;\n");

    for (int kt = 0; kt < ntiles; kt++) {
        asm volatile("cp.async.wait_group 1;\n");
        __syncthreads();

        const uint32_t* As = (const uint32_t*)(smem + (kt % NSTAGE) * A256_STAGE_B);
        const uint32_t* Bs = (const uint32_t*)(smem + NSTAGE * A256_STAGE_B + (kt % NSTAGE) * B_STAGE_B);

        #pragma unroll
        for (int kk2 = 0; kk2 < 16; kk2 += 8) {
            uint32_t af[4][4];
            #pragma unroll
            for (int i = 0; i < 4; i++) {
                int r0 = wm + 16 * i + g;
                af[i][0] = As[(r0)     * A_STRIDE_U32 + kk2 + tg];
                af[i][1] = As[(r0 + 8) * A_STRIDE_U32 + kk2 + tg];
                af[i][2] = As[(r0)     * A_STRIDE_U32 + kk2 + tg + 4];
                af[i][3] = As[(r0 + 8) * A_STRIDE_U32 + kk2 + tg + 4];
            }
            uint32_t bf[8][2];
            #pragma unroll
            for (int j = 0; j < 8; j++) {
                int c0 = wn + 8 * j + g;
                bf[j][0] = Bs[(kk2 + tg)     * B_STRIDE_U32 + c0];
                bf[j][1] = Bs[(kk2 + tg + 4) * B_STRIDE_U32 + c0];
            }
            #pragma unroll
            for (int i = 0; i < 4; i++)
                #pragma unroll
                for (int j = 0; j < 8; j++) {
                    asm volatile(
                        "mma.sync.aligned.m16n8k16.row.col.f32.f16.f16.f32 "
                        "{%0,%1,%2,%3}, {%4,%5,%6,%7}, {%8,%9}, {%0,%1,%2,%3};\n"
                        : "+f"(acc[i][j][0]), "+f"(acc[i][j][1]),
                          "+f"(acc[i][j][2]), "+f"(acc[i][j][3])
                        : "r"(af[i][0]), "r"(af[i][1]), "r"(af[i][2]), "r"(af[i][3]),
                          "r"(bf[j][0]), "r"(bf[j][1]));
                }
        }
        __syncthreads();
        if (kt + 2 < ntiles) stage(kt + 2);
        asm volatile("cp.async.commit_group;\n");
    }

    if (outHalf) {
        __half* C = (__half*)Cb;
        #pragma unroll
        for (int i = 0; i < 4; i++)
            #pragma unroll
            for (int j = 0; j < 8; j++) {
                int r0 = bm + wm + 16 * i + g;
                int c0 = bn + wn + 8 * j + 2 * tg;
                if (c0 < N) {
                    *(uint32_t*)(C + (long)r0 * ldc + c0) =
                        pack_half2(acc[i][j][0] * alpha, acc[i][j][1] * alpha);
                    *(uint32_t*)(C + (long)(r0 + 8) * ldc + c0) =
                        pack_half2(acc[i][j][2] * alpha, acc[i][j][3] * alpha);
                }
            }
    } else {
        float* C = (float*)Cb;
        #pragma unroll
        for (int i = 0; i < 4; i++)
            #pragma unroll
            for (int j = 0; j < 8; j++) {
                int r0 = bm + wm + 16 * i + g;
                int c0 = bn + wn + 8 * j + 2 * tg;
                if (c0 < N) {
                    *(float2*)(C + (long)r0 * ldc + c0) =
                        make_float2(acc[i][j][0] * alpha, acc[i][j][1] * alpha);
                    *(float2*)(C + (long)(r0 + 8) * ldc + c0) =
                        make_float2(acc[i][j][2] * alpha, acc[i][j][3] * alpha);
                }
            }
    }
}

static inline void launch_gemm_s(cudaStream_t st, const __half* A, const uint32_t* B2, void* C,
                                 int M, int N, int K, int lda, int ldb2, int ldc,
                                 long sA, long sB2, long sC, float alpha, int batch,
                                 int outHalf, int mode) {
    dim3 grid((N + 127) / 128, M / 128, batch);
    h16gemm_kernel<<<grid, 128, GEMM_SMEM_BYTES, st>>>(A, B2, C, M, N, K, lda, ldb2, ldc,
                                                       sA, sB2, sC, alpha, outHalf, mode);
}
static inline void launch_gemm256_s(cudaStream_t st, const __half* A, const uint32_t* B2, void* C,
                                    int M, int N, int K, int lda, int ldb2, int ldc,
                                    float alpha, int outHalf) {
    dim3 grid((N + 127) / 128, M / 256, 1);
    h16gemm256_kernel<<<grid, 256, GEMM256_SMEM_BYTES, st>>>(A, B2, C, M, N, K, lda, ldb2, ldc,
                                                             alpha, outHalf);
}

// ---------------- entry ----------------
extern "C" void kernel_launch(void* const* d_in, const int* in_sizes, int n_in,
                              void* d_out, int out_size) {
    const float* hidden      = (const float*)d_in[0];
    // d_in[1] attention_mask: all-ones; unused (pure causal).
    const int*   pos         = (const int*)d_in[2];
    const float* w_in        = (const float*)d_in[3];
    const float* w_post_attn = (const float*)d_in[4];
    const float* w_pre_ff    = (const float*)d_in[5];
    const float* w_post_ff   = (const float*)d_in[6];
    const float* qa_w        = (const float*)d_in[7];
    const float* qa_ln_s     = (const float*)d_in[8];
    const float* qa_ln_b     = (const float*)d_in[9];
    const float* qb_w        = (const float*)d_in[10];
    const float* kv_mqa_w    = (const float*)d_in[11];
    const float* kv_ln_s     = (const float*)d_in[12];
    const float* kv_ln_b     = (const float*)d_in[13];
    const float* kvi_w       = (const float*)d_in[14];
    const float* o_w         = (const float*)d_in[15];
    const float* gate_up_w   = (const float*)d_in[16];
    const float* down_w      = (const float*)d_in[17];
    float* out = (float*)d_out;

    unsigned char* sc = nullptr;
    cudaGetSymbolAddress((void**)&sc, g_scratch);
    float*    scoresF = (float*)(sc + OB_SCORES);
    __half*   Ph      = (__half*)(sc + OB_P);
    __half*   h1h     = (__half*)(sc + OB_H1);
    __half*   qah     = (__half*)(sc + OB_QA);
    __half*   qh      = (__half*)(sc + OB_Q);
    __half*   ckvh    = (__half*)(sc + OB_CKV);
    __half*   kvlnh   = (__half*)(sc + OB_KVLN);
    __half*   kvh     = (__half*)(sc + OB_KV);
    uint32_t* kft2    = (uint32_t*)(sc + OB_KFT);
    uint32_t* v2      = (uint32_t*)(sc + OB_V2);
    __half*   attnoh  = (__half*)(sc + OB_ATTNO);
    float*    attnprojF = (float*)(sc + OB_ATTNPROJ);
    float*    xF      = (float*)(sc + OB_X);
    __half*   h2h     = (__half*)(sc + OB_H2);
    __half*   guh     = (__half*)(sc + OB_GU);
    __half*   acth    = (__half*)(sc + OB_ACT);
    float*    mlpF    = (float*)(sc + OB_MLP);
    uint32_t* Wqa = (uint32_t*)(sc + OB_WQA);
    uint32_t* Wqb = (uint32_t*)(sc + OB_WQB);
    uint32_t* Wkv = (uint32_t*)(sc + OB_WKV);
    uint32_t* Wkvi = (uint32_t*)(sc + OB_WKVI);
    uint32_t* Wo  = (uint32_t*)(sc + OB_WO);
    uint32_t* Wgu = (uint32_t*)(sc + OB_WGU);
    uint32_t* Wdn = (uint32_t*)(sc + OB_WDN);

    static cudaStream_t s2 = nullptr, s3 = nullptr;
    static cudaEvent_t evFork, evFork2, evWsmall, evWbig, evKv;
    static bool init_done = false;
    if (!init_done) {
        cudaStreamCreateWithFlags(&s2, cudaStreamNonBlocking);
        cudaStreamCreateWithFlags(&s3, cudaStreamNonBlocking);
        cudaEventCreateWithFlags(&evFork,   cudaEventDisableTiming);
        cudaEventCreateWithFlags(&evFork2,  cudaEventDisableTiming);
        cudaEventCreateWithFlags(&evWsmall, cudaEventDisableTiming);
        cudaEventCreateWithFlags(&evWbig,   cudaEventDisableTiming);
        cudaEventCreateWithFlags(&evKv,     cudaEventDisableTiming);
        cudaFuncSetAttribute(h16gemm_kernel,
                             cudaFuncAttributeMaxDynamicSharedMemorySize, GEMM_SMEM_BYTES);
        cudaFuncSetAttribute(h16gemm256_kernel,
                             cudaFuncAttributeMaxDynamicSharedMemorySize, GEMM256_SMEM_BYTES);
        init_done = true;
    }
    cudaStream_t s0 = 0;

    auto cw = [&](cudaStream_t st, const float* s, uint32_t* d, int K, int Nout, int lds) {
        long total = (long)(K / 2) * (Nout / 4);
        conv_w_kernel<<<(int)((total + 255) / 256), 256, 0, st>>>(s, d, K / 2, Nout, lds, 0);
    };

    // ---- fork s2: weight conversions ----
    cudaEventRecord(evFork, s0);
    cudaStreamWaitEvent(s2, evFork, 0);
    cw(s2, qa_w,      Wqa,  HID_, QL_,        QL_);
    cw(s2, qb_w,      Wqb,  QL_,  HQH_,       HQH_);
    cw(s2, kv_mqa_w,  Wkv,  HID_, CKV_,       CKV_);
    cw(s2, kvi_w,     Wkvi, KVL_, KVOUT_,     H_ * (NOPE_ + VD_));
    cudaEventRecord(evWsmall, s2);
    cw(s2, o_w,       Wo,   HID_, HID_,       HID_);
    cw(s2, gate_up_w, Wgu,  HID_, 2 * INTER_, 2 * INTER_);
    cw(s2, down_w,    Wdn,  INTER_, HID_,     HID_);
    cudaEventRecord(evWbig, s2);

    // ---- origin: h1 = rms(hidden)*w_in ----
    rms_kernel<<<S_, 256, 0, s0>>>(hidden, nullptr, w_in, h1h, HID_, 1);
    cudaEventRecord(evFork2, s0);

    // ---- fork s3: kv chain ----
    cudaStreamWaitEvent(s3, evFork2, 0);
    cudaStreamWaitEvent(s3, evWsmall, 0);
    launch_gemm256_s(s3, h1h, Wkv, ckvh, S_, CKV_, HID_, HID_, CKV_, CKV_, 1.f, 1);
    ln_kernel<<<S_, 256, 0, s3>>>(ckvh, kv_ln_s, kv_ln_b, kvlnh, KVL_, CKV_, KVL_);
    launch_gemm_s(s3, kvlnh, Wkvi, kvh, S_, KVOUT_, KVL_, KVL_, KVOUT_, KVOUT_, 0, 0, 0, 1.f, 1, 1, 0);
    build_kft_kernel<<<S_, 96, 0, s3>>>(kvh, ckvh, pos, kft2);
    build_v2_kernel<<<(S_ / 2 * VD_ + 255) / 256, 256, 0, s3>>>(kvh, v2);
    cudaEventRecord(evKv, s3);

    // ---- origin: q chain ----
    cudaStreamWaitEvent(s0, evWsmall, 0);
    launch_gemm256_s(s0, h1h, Wqa, qah, S_, QL_, HID_, HID_, QL_, QL_, 1.f, 1);
    ln_kernel<<<S_, 256, 0, s0>>>(qah, qa_ln_s, qa_ln_b, qah, QL_, QL_, QL_);
    launch_gemm256_s(s0, qah, Wqb, qh, S_, HQH_, QL_, QL_, HQH_, HQH_, 1.f, 1);
    rope_q_kernel<<<S_, 512, 0, s0>>>(qh, pos);

    // ---- join kv; attention ----
    cudaStreamWaitEvent(s0, evKv, 0);
    const float scale = 0.07216878364870323f;   // 192^-0.5
    launch_gemm_s(s0, qh, kft2, scoresF, S_, S_, KFD_, HQH_, S_, S_,
                  (long)QH_, 0L, (long)S_ * S_, scale, H_, 0, 1);
    softmax_kernel<<<dim3(S_, H_), 256, 0, s0>>>(scoresF, Ph);
    launch_gemm_s(s0, Ph, v2, attnoh, S_, VD_, S_, S_, VD_, HID_,
                  (long)S_ * S_, 0L, (long)VD_, 1.f, H_, 1, 2);

    // ---- join big weights; o-proj + MLP ----
    cudaStreamWaitEvent(s0, evWbig, 0);
    launch_gemm256_s(s0, attnoh, Wo, attnprojF, S_, HID_, HID_, HID_, HID_, HID_, 1.f, 0);
    rms_kernel<<<S_, 256, 0, s0>>>(attnprojF, hidden, w_post_attn, xF, HID_, 0);
    rms_kernel<<<S_, 256, 0, s0>>>(xF, nullptr, w_pre_ff, h2h, HID_, 1);
    launch_gemm256_s(s0, h2h, Wgu, guh, S_, 2 * INTER_, HID_, HID_, 2 * INTER_, 2 * INTER_, 1.f, 1);
    silu_mul_kernel<<<(S_ * INTER_) / 256, 256, 0, s0>>>(guh, acth);
    launch_gemm256_s(s0, acth, Wdn, mlpF, S_, HID_, INTER_, INTER_, HID_, HID_, 1.f, 0);
    rms_kernel<<<S_, 256, 0, s0>>>(mlpF, xF, w_post_ff, out, HID_, 0);
}